// round 12
// baseline (speedup 1.0000x reference)
#include <cuda_runtime.h>
#include <cuda_bf16.h>
#include <math.h>

#define TOTAL 160
#define NB    16
#define NGR   4
#define DIM   1024
#define CIN   834
#define GF    256
#define SSP   1568   // 8*14*14

__constant__ int c_off[NB + 1] = {0, 6, 20, 30, 38, 54, 66, 75, 86, 93,
                                  106, 116, 126, 134, 146, 152, 160};

// Scratch (device globals) — split-K partial buffers are summed by consumers.
__device__ float g_emb [TOTAL * NGR * GF];
__device__ float g_emb2[TOTAL * NGR * GF];
__device__ float g_q   [TOTAL * NGR * CIN];
__device__ float g_adj [TOTAL * NGR * SSP];
__device__ float g_adj2[TOTAL * NGR * SSP];
__device__ float g_r   [TOTAL * NGR * CIN];
__device__ float g_r2  [TOTAL * NGR * CIN];
__device__ float g_upd [TOTAL * NGR * GF];
__device__ float g_upd2[TOTAL * NGR * GF];
__device__ float g_inv [TOTAL * NGR];

// ---- truncation-based bf16 split + PRMT pack ----
__device__ __forceinline__ unsigned prmt_hi(unsigned a, unsigned b) {
    unsigned r;
    asm("prmt.b32 %0, %1, %2, 0x7632;" : "=r"(r) : "r"(a), "r"(b));
    return r;
}
__device__ __forceinline__ void packhl(float a, float b, unsigned& hw, unsigned& lw) {
    const unsigned ua = __float_as_uint(a), ub = __float_as_uint(b);
    hw = prmt_hi(ua, ub);
    const float la = a - __uint_as_float(ua & 0xFFFF0000u);   // exact residual
    const float lb = b - __uint_as_float(ub & 0xFFFF0000u);
    lw = prmt_hi(__float_as_uint(la), __float_as_uint(lb));
}
__device__ __forceinline__ void mma16(float* d, const unsigned* a, const unsigned* b) {
    asm volatile(
        "mma.sync.aligned.m16n8k16.row.col.f32.bf16.bf16.f32 "
        "{%0,%1,%2,%3}, {%4,%5,%6,%7}, {%8,%9}, {%0,%1,%2,%3};\n"
        : "+f"(d[0]), "+f"(d[1]), "+f"(d[2]), "+f"(d[3])
        : "r"(a[0]), "r"(a[1]), "r"(a[2]), "r"(a[3]), "r"(b[0]), "r"(b[1]));
}
__device__ __forceinline__ void ldsm4(unsigned& r0, unsigned& r1, unsigned& r2,
                                      unsigned& r3, unsigned addr) {
    asm volatile("ldmatrix.sync.aligned.m8n8.x4.shared.b16 {%0,%1,%2,%3}, [%4];\n"
                 : "=r"(r0), "=r"(r1), "=r"(r2), "=r"(r3) : "r"(addr));
}
__device__ __forceinline__ void ldsm4t(unsigned& r0, unsigned& r1, unsigned& r2,
                                       unsigned& r3, unsigned addr) {
    asm volatile("ldmatrix.sync.aligned.m8n8.x4.trans.shared.b16 {%0,%1,%2,%3}, [%4];\n"
                 : "=r"(r0), "=r"(r1), "=r"(r2), "=r"(r3) : "r"(addr));
}

// ---------------------------------------------------------------------------
// fp32-accurate GEMM via 3-term bf16 split, ldmatrix fragment loads.
// C[M,N] = A[M,K] * op(B). TB=true: B[N,K] (BN=64); TB=false: B[K,N].
// ASUM: A := A + A2 elementwise during fill. ASCALE: per-row A scale.
// ADDEND: epilogue adds add[] (and add2[] if non-null).
// ---------------------------------------------------------------------------
template<int BN, bool TB, bool RELU, bool BIAS, bool ADDEND, bool ASUM, bool ASCALE>
__device__ __forceinline__ void core(
    const float* __restrict__ A, const float* __restrict__ A2, int lda,
    const float* __restrict__ B, int ldb,
    float* __restrict__ C, int ldc,
    int M, int N, int K,
    const float* __restrict__ bias,
    const float* __restrict__ add, const float* __restrict__ add2, int ldadd,
    const float* __restrict__ ascale)
{
    constexpr int BM = 64, BK = 32;
    constexpr int AW  = 20;
    constexpr int BTW = 20;
    constexpr int BW2 = BN / 2 + 4;
    constexpr int WN  = BN / 4;
    constexpr int NI  = WN / 8;
    constexpr int BWRD = TB ? (BN * BTW) : (32 * BW2);
    constexpr int WS   = 2 * BM * AW + 2 * BWRD;
    static_assert(!TB || BN == 64, "TB path assumes BN==64");

    extern __shared__ unsigned smw[];
    const unsigned sbase = (unsigned)__cvta_generic_to_shared(smw);

    const int tid  = threadIdx.x;
    const int lane = tid & 31;
    const int wid  = tid >> 5;
    const int wm   = wid & 1;
    const int wn   = wid >> 1;
    const int gq   = lane >> 2;
    const int tq   = lane & 3;
    const int m0   = blockIdx.y * BM;
    const int n0   = blockIdx.x * BN;

    const int arow = tid >> 2, ac0 = (tid & 3) * 8;
    const int tkrow = tid >> 3, tn0 = (tid & 7) * (BN / 8);

    float ascl = 1.f;
    if (ASCALE && (m0 + arow) < M) ascl = ascale[m0 + arow];

    float ra[8], rb[16];

    auto loadA = [&](int kt) {
        const bool rok = (m0 + arow) < M;
        const long base = (long)(m0 + arow) * lda + kt + ac0;
#pragma unroll
        for (int j = 0; j < 4; j++) {
            float2 v = make_float2(0.f, 0.f);
            if (rok && (kt + ac0 + 2 * j) < K) {
                v = *reinterpret_cast<const float2*>(A + base + 2 * j);
                if (ASUM) {
                    float2 w = *reinterpret_cast<const float2*>(A2 + base + 2 * j);
                    v.x += w.x; v.y += w.y;
                }
            }
            if (ASCALE) { v.x *= ascl; v.y *= ascl; }
            ra[2 * j] = v.x; ra[2 * j + 1] = v.y;
        }
    };
    auto loadB = [&](int kt) {
        if (TB) {
            const bool rok = (n0 + arow) < N;
            const float* p = B + (long)(n0 + arow) * ldb + kt + ac0;
#pragma unroll
            for (int j = 0; j < 4; j++) {
                float2 v = make_float2(0.f, 0.f);
                if (rok && (kt + ac0 + 2 * j) < K) v = *reinterpret_cast<const float2*>(p + 2 * j);
                rb[2 * j] = v.x; rb[2 * j + 1] = v.y;
            }
        } else {
            const bool kok = (kt + tkrow) < K;
            const float* p = B + (long)(kt + tkrow) * ldb + n0 + tn0;
#pragma unroll
            for (int j = 0; j < BN / 16; j++) {
                float2 v = make_float2(0.f, 0.f);
                if (kok && (n0 + tn0 + 2 * j) < N) v = *reinterpret_cast<const float2*>(p + 2 * j);
                rb[2 * j] = v.x; rb[2 * j + 1] = v.y;
            }
        }
    };
    auto storeStage = [&](int st) {
        unsigned* S = smw + st * WS;
        {
            unsigned hw[4], lw[4];
#pragma unroll
            for (int j = 0; j < 4; j++) packhl(ra[2 * j], ra[2 * j + 1], hw[j], lw[j]);
            const int w0 = arow * AW + (tid & 3) * 4;
            *reinterpret_cast<uint4*>(S + w0)           = make_uint4(hw[0], hw[1], hw[2], hw[3]);
            *reinterpret_cast<uint4*>(S + BM * AW + w0) = make_uint4(lw[0], lw[1], lw[2], lw[3]);
        }
        unsigned* SB = S + 2 * BM * AW;
        if (TB) {
            unsigned hw[4], lw[4];
#pragma unroll
            for (int j = 0; j < 4; j++) packhl(rb[2 * j], rb[2 * j + 1], hw[j], lw[j]);
            const int w0 = arow * BTW + (tid & 3) * 4;
            *reinterpret_cast<uint4*>(SB + w0)        = make_uint4(hw[0], hw[1], hw[2], hw[3]);
            *reinterpret_cast<uint4*>(SB + BWRD + w0) = make_uint4(lw[0], lw[1], lw[2], lw[3]);
        } else {
            unsigned hw[8], lw[8];
#pragma unroll
            for (int j = 0; j < BN / 16; j++) packhl(rb[2 * j], rb[2 * j + 1], hw[j], lw[j]);
            const int w0 = tkrow * BW2 + (tid & 7) * (BN / 16);
            *reinterpret_cast<uint4*>(SB + w0)        = make_uint4(hw[0], hw[1], hw[2], hw[3]);
            *reinterpret_cast<uint4*>(SB + BWRD + w0) = make_uint4(lw[0], lw[1], lw[2], lw[3]);
            if (BN == 128) {
                *reinterpret_cast<uint4*>(SB + w0 + 4)        = make_uint4(hw[4], hw[5], hw[6], hw[7]);
                *reinterpret_cast<uint4*>(SB + BWRD + w0 + 4) = make_uint4(lw[4], lw[5], lw[6], lw[7]);
            }
        }
    };

    const int m8 = lane >> 3, r8 = lane & 7;
    const unsigned aoff = ((wm * 32 + (m8 & 1) * 8 + r8) * AW + (m8 >> 1) * 4) * 4;
    unsigned boff;
    if (TB) boff = (2 * BM * AW + (wn * WN + (m8 >> 1) * 8 + r8) * BTW + (m8 & 1) * 4) * 4;
    else    boff = (2 * BM * AW + ((m8 & 1) * 8 + r8) * BW2) * 4 + (wn * WN + (m8 >> 1) * 8) * 2;

    float acc[2][NI][4];
#pragma unroll
    for (int mi = 0; mi < 2; mi++)
#pragma unroll
        for (int ni = 0; ni < NI; ni++)
#pragma unroll
            for (int q = 0; q < 4; q++) acc[mi][ni][q] = 0.f;

    loadA(0); loadB(0);
    storeStage(0);
    __syncthreads();

    int st = 0;
    for (int kt = 0; kt < K; kt += BK) {
        const bool notlast = (kt + BK) < K;
        if (notlast) { loadA(kt + BK); loadB(kt + BK); }

        const unsigned stb = sbase + st * WS * 4;
#pragma unroll
        for (int kk2 = 0; kk2 < 2; kk2++) {
            unsigned ah[2][4], al[2][4];
#pragma unroll
            for (int mi = 0; mi < 2; mi++) {
                const unsigned ad = stb + aoff + mi * (16 * AW * 4) + kk2 * 32;
                ldsm4(ah[mi][0], ah[mi][1], ah[mi][2], ah[mi][3], ad);
                ldsm4(al[mi][0], al[mi][1], al[mi][2], al[mi][3], ad + BM * AW * 4);
            }
            unsigned bh[NI][2], bl[NI][2];
            if (TB) {
                const unsigned bd = stb + boff + kk2 * 32;
                ldsm4(bh[0][0], bh[0][1], bh[1][0], bh[1][1], bd);
                ldsm4(bl[0][0], bl[0][1], bl[1][0], bl[1][1], bd + BWRD * 4);
            } else {
#pragma unroll
                for (int nb = 0; nb < NI / 2; nb++) {
                    const unsigned bd = stb + boff + kk2 * (16 * BW2 * 4) + nb * 32;
                    ldsm4t(bh[2*nb][0], bh[2*nb][1], bh[2*nb+1][0], bh[2*nb+1][1], bd);
                    ldsm4t(bl[2*nb][0], bl[2*nb][1], bl[2*nb+1][0], bl[2*nb+1][1], bd + BWRD * 4);
                }
            }
#pragma unroll
            for (int mi = 0; mi < 2; mi++)
#pragma unroll
                for (int ni = 0; ni < NI; ni++) {
                    mma16(acc[mi][ni], al[mi], bh[ni]);
                    mma16(acc[mi][ni], ah[mi], bl[ni]);
                    mma16(acc[mi][ni], ah[mi], bh[ni]);
                }
        }

        if (notlast) {
            storeStage(st ^ 1);
            __syncthreads();
            st ^= 1;
        }
    }

    // epilogue
#pragma unroll
    for (int mi = 0; mi < 2; mi++)
#pragma unroll
        for (int ni = 0; ni < NI; ni++)
#pragma unroll
            for (int q = 0; q < 4; q++) {
                const int m = m0 + wm * 32 + mi * 16 + gq + (q >> 1) * 8;
                const int n = n0 + wn * WN + ni * 8 + tq * 2 + (q & 1);
                if (m < M && n < N) {
                    float v = acc[mi][ni][q];
                    if (BIAS   && bias) v += bias[n];
                    if (ADDEND && add)  v += add[(long)m * ldadd + n];
                    if (ADDEND && add2) v += add2[(long)m * ldadd + n];
                    if (RELU) v = fmaxf(v, 0.f);
                    C[(long)m * ldc + n] = v;
                }
            }
}

// ---------------------------------------------------------------------------
// Stage kernels
// ---------------------------------------------------------------------------

// emb = actor @ Wa^T + ba ; split-K x2 into emb / emb2 (consumers sum)
__global__ void __launch_bounds__(256, 2)
k_emb(const float* __restrict__ A, const float* __restrict__ Wa,
      const float* __restrict__ ba) {
    const int ks = blockIdx.z;
    const int koff = ks * 512;
    core<64, true, false, true, false, false, false>(
        A + koff, nullptr, DIM, Wa + koff, DIM,
        ks == 0 ? g_emb : g_emb2, NGR * GF,
        TOTAL, NGR * GF, 512, ks == 0 ? ba : nullptr, nullptr, nullptr, 0, nullptr);
}

// q = (emb+emb2) @ Wc
__global__ void __launch_bounds__(256, 2)
k_q(const float* __restrict__ Wc) {
    const int g = blockIdx.z;
    core<64, false, false, false, false, true, false>(
        g_emb + g * GF, g_emb2 + g * GF, NGR * GF,
        Wc + (long)g * GF * CIN, CIN,
        g_q + g * CIN, NGR * CIN,
        TOTAL, CIN, GF, nullptr, nullptr, nullptr, 0, nullptr);
}

// logits = q @ fm[b] ; split-K x2 into adj / adj2
__global__ void __launch_bounds__(256, 2)
k_logits(const float* __restrict__ fm) {
    const int z   = blockIdx.z;
    const int b   = z & 15;
    const int ks  = z >> 4;
    const int off = c_off[b];
    const int cnt = c_off[b + 1] - off;
    const int koff = ks ? 416 : 0;
    const int kext = ks ? 418 : 416;
    core<128, false, false, false, false, false, false>(
        g_q + (long)off * NGR * CIN + koff, nullptr, CIN,
        fm + (long)b * CIN * SSP + (long)koff * SSP, SSP,
        (ks == 0 ? g_adj : g_adj2) + (long)off * NGR * SSP, SSP,
        cnt * NGR, SSP, kext, nullptr, nullptr, nullptr, 0, nullptr);
}

// exp(adj+adj2) -> g_adj ; 1/sum -> g_inv (applied in k_r's A fill)
__global__ void k_softmax() {
    const int row = blockIdx.x;
    float* __restrict__ p0 = g_adj  + (long)row * SSP;
    const float* __restrict__ p1 = g_adj2 + (long)row * SSP;
    const int t = threadIdx.x;
    __shared__ float sh[8];

    float sum = 0.f;
    for (int s = t; s < SSP; s += 256) {
        const float e = __expf(p0[s] + p1[s]);
        p0[s] = e;
        sum += e;
    }
#pragma unroll
    for (int o = 16; o; o >>= 1) sum += __shfl_xor_sync(0xffffffffu, sum, o);
    if ((t & 31) == 0) sh[t >> 5] = sum;
    __syncthreads();
    if (t == 0) {
        float v = 0.f;
        for (int i = 0; i < 8; i++) v += sh[i];
        g_inv[row] = 1.f / v;
    }
}

// r = (inv*adj) @ fm[b]^T ; split over s x2 into r / r2
__global__ void __launch_bounds__(256, 2)
k_r(const float* __restrict__ fm) {
    const int z   = blockIdx.z;
    const int b   = z & 15;
    const int ks  = z >> 4;
    const int off = c_off[b];
    const int cnt = c_off[b + 1] - off;
    const int soff = ks * 784;
    core<64, true, false, false, false, false, true>(
        g_adj + (long)off * NGR * SSP + soff, nullptr, SSP,
        fm + (long)b * CIN * SSP + soff, SSP,
        (ks == 0 ? g_r : g_r2) + (long)off * NGR * CIN, CIN,
        cnt * NGR, CIN, 784, nullptr, nullptr, nullptr, 0, g_inv + off * NGR);
}

// upd = (r+r2) @ Wc^T + bc + emb+emb2 ; split-K x2 into upd / upd2
__global__ void __launch_bounds__(256, 2)
k_upd(const float* __restrict__ Wc, const float* __restrict__ bc) {
    const int g  = blockIdx.z & 3;
    const int ks = blockIdx.z >> 2;
    const int koff = ks ? 416 : 0;
    const int kext = ks ? 418 : 416;
    core<64, true, false, true, true, true, false>(
        g_r + g * CIN + koff, g_r2 + g * CIN + koff, NGR * CIN,
        Wc + (long)g * GF * CIN + koff, CIN,
        (ks == 0 ? g_upd : g_upd2) + g * GF, NGR * GF,
        TOTAL, GF, kext,
        ks == 0 ? bc + g * GF : nullptr,
        ks == 0 ? g_emb + g * GF : nullptr,
        ks == 0 ? g_emb2 + g * GF : nullptr, NGR * GF, nullptr);
}

// out = relu((upd+upd2) @ Wh^T)
__global__ void __launch_bounds__(256, 2)
k_head(const float* __restrict__ Wh, float* __restrict__ out) {
    const int g = blockIdx.z;
    core<64, true, true, false, false, true, false>(
        g_upd + g * GF, g_upd2 + g * GF, NGR * GF,
        Wh + (long)g * GF * GF, GF,
        out + g * GF, NGR * GF,
        TOTAL, GF, GF, nullptr, nullptr, nullptr, 0, nullptr);
}

// ---------------------------------------------------------------------------
extern "C" void kernel_launch(void* const* d_in, const int* in_sizes, int n_in,
                              void* d_out, int out_size) {
    const float* actor = (const float*)d_in[0];   // [160,1024]
    const float* fm    = (const float*)d_in[1];   // [16,834,1568]
    const float* Wa    = (const float*)d_in[2];   // [4,256,1024]
    const float* ba    = (const float*)d_in[3];   // [4,256]
    const float* Wc    = (const float*)d_in[4];   // [4,256,834]
    const float* bc    = (const float*)d_in[5];   // [4,256]
    const float* Wh    = (const float*)d_in[6];   // [4,256,256]
    float* out = (float*)d_out;                   // [160,1024]

    constexpr int S_TB64  = 2 * (2 * 64 * 20 + 2 * 64 * 20) * 4;   // 40960
    constexpr int S_NT64  = 2 * (2 * 64 * 20 + 2 * 32 * 36) * 4;   // 38912
    constexpr int S_NT128 = 2 * (2 * 64 * 20 + 2 * 32 * 68) * 4;   // 55296

    cudaFuncSetAttribute(k_logits, cudaFuncAttributeMaxDynamicSharedMemorySize, S_NT128);

    const dim3 blk(256);
    k_emb    <<<dim3(16, 3, 2),   blk, S_TB64 >>>(actor, Wa, ba);
    k_q      <<<dim3(14, 3, NGR), blk, S_NT64 >>>(Wc);
    k_logits <<<dim3(13, 1, 32),  blk, S_NT128>>>(fm);
    k_softmax<<<TOTAL * NGR, 256>>>();
    k_r      <<<dim3(14, 1, 32),  blk, S_TB64 >>>(fm);
    k_upd    <<<dim3(4, 3, 8),    blk, S_TB64 >>>(Wc, bc);
    k_head   <<<dim3(4, 3, NGR),  blk, S_TB64 >>>(Wh, out);
}